// round 1
// baseline (speedup 1.0000x reference)
#include <cuda_runtime.h>

// Problem constants (from reference): B=4, C=64, N=512, H=128, 2C=128.
#define B_ 4
#define C_ 64
#define N_ 512
#define H_ 128

// Scratch: A[b][h][n] = b1[h] + sum_c x[b,c,n]*W1[c][h]   (left/row term, b1 folded)
//          Bv[b][h][n] =         sum_c x[b,c,n]*W1[C+c][h] (right/col term)
// Stored h-major so the pairwise kernel's shared-tile loads are contiguous in n.
__device__ float g_A[B_ * H_ * N_];
__device__ float g_Bv[B_ * H_ * N_];

// ---------------------------------------------------------------------------
// Kernel 1: tiny GEMM  (x^T @ [W1a | W1b])  -> g_A, g_Bv  (h-major)
// grid: (N/128, 256/16, B)  block: 128 threads (one n per thread, 16 hu's)
// hu in [0,128) -> A with weights W1[c][hu]; hu in [128,256) -> Bv with W1[64+c][hu-128]
// ---------------------------------------------------------------------------
__global__ void precompute_AB(const float* __restrict__ x,
                              const float* __restrict__ W1,
                              const float* __restrict__ b1) {
    __shared__ float Wsh[C_ * 16];  // [c][k], k = hu - hu0

    const int tid = threadIdx.x;
    const int n   = blockIdx.x * 128 + tid;
    const int hu0 = blockIdx.y * 16;
    const int b   = blockIdx.z;

    // Stage the 64x16 weight slice (uniform branch: chunk is entirely A or entirely Bv)
    #pragma unroll
    for (int r = 0; r < 8; r++) {
        int idx = tid + 128 * r;          // 0..1023
        int c = idx >> 4;
        int k = idx & 15;
        int hu = hu0 + k;
        float w = (hu < H_) ? W1[c * H_ + hu]
                            : W1[(C_ + c) * H_ + (hu - H_)];
        Wsh[idx] = w;
    }
    __syncthreads();

    float acc[16];
    #pragma unroll
    for (int k = 0; k < 16; k++) acc[k] = 0.0f;

    const float* xp = x + (b * C_) * N_ + n;
    #pragma unroll 4
    for (int c = 0; c < C_; c++) {
        float xv = xp[c * N_];
        const float4* w4 = (const float4*)(Wsh + c * 16);
        float4 w0 = w4[0], w1 = w4[1], w2 = w4[2], w3 = w4[3];
        acc[0]  = fmaf(xv, w0.x, acc[0]);  acc[1]  = fmaf(xv, w0.y, acc[1]);
        acc[2]  = fmaf(xv, w0.z, acc[2]);  acc[3]  = fmaf(xv, w0.w, acc[3]);
        acc[4]  = fmaf(xv, w1.x, acc[4]);  acc[5]  = fmaf(xv, w1.y, acc[5]);
        acc[6]  = fmaf(xv, w1.z, acc[6]);  acc[7]  = fmaf(xv, w1.w, acc[7]);
        acc[8]  = fmaf(xv, w2.x, acc[8]);  acc[9]  = fmaf(xv, w2.y, acc[9]);
        acc[10] = fmaf(xv, w2.z, acc[10]); acc[11] = fmaf(xv, w2.w, acc[11]);
        acc[12] = fmaf(xv, w3.x, acc[12]); acc[13] = fmaf(xv, w3.y, acc[13]);
        acc[14] = fmaf(xv, w3.z, acc[14]); acc[15] = fmaf(xv, w3.w, acc[15]);
    }

    if (hu0 < H_) {
        #pragma unroll
        for (int k = 0; k < 16; k++) {
            int h = hu0 + k;
            g_A[((b * H_) + h) * N_ + n] = acc[k] + b1[h];
        }
    } else {
        #pragma unroll
        for (int k = 0; k < 16; k++) {
            int h = hu0 + k - H_;
            g_Bv[((b * H_) + h) * N_ + n] = acc[k];
        }
    }
}

// ---------------------------------------------------------------------------
// Kernel 2: y[b,i,j] = (j>i) * (b2 + sum_h relu(A[b,i,h] + Bv[b,j,h]) * W2[h])
// grid: (N/64 j-tiles, N/64 i-tiles, B)  block: 256 threads
// 64x64 output tile, 4x4 register tile/thread, h staged in 2 chunks of 64.
// Tiles with Jt < It are pure zero-fill (output is poisoned, must be written).
// ---------------------------------------------------------------------------
__global__ void __launch_bounds__(256) pairwise_score(
        const float* __restrict__ W2,
        const float* __restrict__ b2,
        float* __restrict__ out) {
    const int Jt  = blockIdx.x;
    const int It  = blockIdx.y;
    const int b   = blockIdx.z;
    const int tid = threadIdx.x;
    float* outb = out + b * N_ * N_;

    if (Jt < It) {  // strictly below diagonal: all zeros (uniform branch, no syncs used)
        const float4 z = make_float4(0.f, 0.f, 0.f, 0.f);
        #pragma unroll
        for (int r = 0; r < 4; r++) {
            int l  = tid + 256 * r;     // float4 index 0..1023
            int ii = l >> 4;            // 0..63
            int j4 = l & 15;            // 0..15
            *(float4*)(outb + (It * 64 + ii) * N_ + Jt * 64 + j4 * 4) = z;
        }
        return;
    }

    __shared__ float As[64 * 64];   // [hh][ii]
    __shared__ float Bs[64 * 64];   // [hh][jj]
    __shared__ float Wsh[H_];

    if (tid < H_) Wsh[tid] = W2[tid];

    float acc[4][4];
    #pragma unroll
    for (int p = 0; p < 4; p++)
        #pragma unroll
        for (int q = 0; q < 4; q++) acc[p][q] = 0.0f;

    const int ti4 = tid >> 4;   // 0..15, i-local = 4*ti4 + p
    const int tj4 = tid & 15;   // 0..15, j-local = 4*tj4 + q

    #pragma unroll
    for (int hb = 0; hb < 2; hb++) {
        __syncthreads();
        const float* Ag = g_A  + ((b * H_) + hb * 64) * N_ + It * 64;
        const float* Bg = g_Bv + ((b * H_) + hb * 64) * N_ + Jt * 64;
        #pragma unroll
        for (int r = 0; r < 4; r++) {
            int l  = tid + 256 * r;   // float4 index 0..1023
            int hh = l >> 4;
            int i4 = l & 15;
            *(float4*)(As + hh * 64 + i4 * 4) = *(const float4*)(Ag + hh * N_ + i4 * 4);
            *(float4*)(Bs + hh * 64 + i4 * 4) = *(const float4*)(Bg + hh * N_ + i4 * 4);
        }
        __syncthreads();

        #pragma unroll 2
        for (int hh = 0; hh < 64; hh++) {
            float4 av = *(const float4*)(As + hh * 64 + ti4 * 4);
            float4 bv = *(const float4*)(Bs + hh * 64 + tj4 * 4);
            float  w  = Wsh[hb * 64 + hh];
            float a_[4] = {av.x, av.y, av.z, av.w};
            float b_[4] = {bv.x, bv.y, bv.z, bv.w};
            #pragma unroll
            for (int p = 0; p < 4; p++)
                #pragma unroll
                for (int q = 0; q < 4; q++) {
                    float u = a_[p] + b_[q];
                    acc[p][q] = fmaf(fmaxf(u, 0.0f), w, acc[p][q]);
                }
        }
    }

    const float bias2 = b2[0];
    const int i0 = It * 64 + ti4 * 4;
    const int j0 = Jt * 64 + tj4 * 4;

    if (Jt > It) {  // strictly above diagonal: no mask needed
        #pragma unroll
        for (int p = 0; p < 4; p++) {
            float4 v = make_float4(acc[p][0] + bias2, acc[p][1] + bias2,
                                   acc[p][2] + bias2, acc[p][3] + bias2);
            *(float4*)(outb + (i0 + p) * N_ + j0) = v;
        }
    } else {        // diagonal tile: apply strict upper-triangle mask j > i
        #pragma unroll
        for (int p = 0; p < 4; p++) {
            int i = i0 + p;
            float4 v;
            v.x = (j0 + 0 > i) ? (acc[p][0] + bias2) : 0.0f;
            v.y = (j0 + 1 > i) ? (acc[p][1] + bias2) : 0.0f;
            v.z = (j0 + 2 > i) ? (acc[p][2] + bias2) : 0.0f;
            v.w = (j0 + 3 > i) ? (acc[p][3] + bias2) : 0.0f;
            *(float4*)(outb + i * N_ + j0) = v;
        }
    }
}

// ---------------------------------------------------------------------------
// Inputs (metadata order): 0:x (B,C,N) f32, 1:W1 (2C,H) f32, 2:b1 (H) f32,
//                          3:W2 (H,1) f32, 4:b2 (1) f32.  out: (B,N,N) f32.
// ---------------------------------------------------------------------------
extern "C" void kernel_launch(void* const* d_in, const int* in_sizes, int n_in,
                              void* d_out, int out_size) {
    const float* x  = (const float*)d_in[0];
    const float* W1 = (const float*)d_in[1];
    const float* b1 = (const float*)d_in[2];
    const float* W2 = (const float*)d_in[3];
    const float* b2 = (const float*)d_in[4];
    float* out = (float*)d_out;

    dim3 g1(N_ / 128, (2 * H_) / 16, B_);   // (4, 16, 4)
    precompute_AB<<<g1, 128>>>(x, W1, b1);

    dim3 g2(N_ / 64, N_ / 64, B_);          // (8, 8, 4)
    pairwise_score<<<g2, 256>>>(W2, b2, out);
}

// round 2
// speedup vs baseline: 1.0749x; 1.0749x over previous
#include <cuda_runtime.h>

// Problem constants: B=4, C=64, N=512, H=128, 2C=128.
#define B_ 4
#define C_ 64
#define N_ 512
#define H_ 128

// Scratch (h-major): A[b][h][n] = b1[h] + sum_c x[b,c,n]*W1[c][h]
//                    Bv[b][h][n] =        sum_c x[b,c,n]*W1[C+c][h]
__device__ float g_A[B_ * H_ * N_];
__device__ float g_Bv[B_ * H_ * N_];

// ---- packed f32x2 helpers (sm_100+) ---------------------------------------
__device__ __forceinline__ unsigned long long f32x2_add(unsigned long long a,
                                                        unsigned long long b) {
    unsigned long long r;
    asm("add.rn.f32x2 %0, %1, %2;" : "=l"(r) : "l"(a), "l"(b));
    return r;
}
__device__ __forceinline__ unsigned long long f32x2_fma(unsigned long long a,
                                                        unsigned long long b,
                                                        unsigned long long c) {
    unsigned long long r;
    asm("fma.rn.f32x2 %0, %1, %2, %3;" : "=l"(r) : "l"(a), "l"(b), "l"(c));
    return r;
}
#define ABS2_MASK 0x7FFFFFFF7FFFFFFFULL

// ---------------------------------------------------------------------------
// Kernel 1: x^T @ [W1a | W1b] -> g_A, g_Bv (h-major).
// grid (N/256, 16, B), 256 threads; thread owns one n, 16 hu's.
// ---------------------------------------------------------------------------
__global__ void __launch_bounds__(256) precompute_AB(
        const float* __restrict__ x,
        const float* __restrict__ W1,
        const float* __restrict__ b1) {
    __shared__ float Wsh[C_ * 16];  // [c][k]

    const int tid = threadIdx.x;
    const int n   = blockIdx.x * 256 + tid;
    const int hu0 = blockIdx.y * 16;
    const int b   = blockIdx.z;

    #pragma unroll
    for (int r = 0; r < 4; r++) {
        int idx = tid + 256 * r;          // 0..1023
        int c = idx >> 4;
        int k = idx & 15;
        int hu = hu0 + k;
        Wsh[idx] = (hu < H_) ? W1[c * H_ + hu]
                             : W1[(C_ + c) * H_ + (hu - H_)];
    }
    __syncthreads();

    float acc[16];
    #pragma unroll
    for (int k = 0; k < 16; k++) acc[k] = 0.0f;

    const float* xp = x + (b * C_) * N_ + n;
    #pragma unroll 4
    for (int c = 0; c < C_; c++) {
        float xv = xp[c * N_];
        const float4* w4 = (const float4*)(Wsh + c * 16);
        float4 w0 = w4[0], w1 = w4[1], w2 = w4[2], w3 = w4[3];
        acc[0]  = fmaf(xv, w0.x, acc[0]);  acc[1]  = fmaf(xv, w0.y, acc[1]);
        acc[2]  = fmaf(xv, w0.z, acc[2]);  acc[3]  = fmaf(xv, w0.w, acc[3]);
        acc[4]  = fmaf(xv, w1.x, acc[4]);  acc[5]  = fmaf(xv, w1.y, acc[5]);
        acc[6]  = fmaf(xv, w1.z, acc[6]);  acc[7]  = fmaf(xv, w1.w, acc[7]);
        acc[8]  = fmaf(xv, w2.x, acc[8]);  acc[9]  = fmaf(xv, w2.y, acc[9]);
        acc[10] = fmaf(xv, w2.z, acc[10]); acc[11] = fmaf(xv, w2.w, acc[11]);
        acc[12] = fmaf(xv, w3.x, acc[12]); acc[13] = fmaf(xv, w3.y, acc[13]);
        acc[14] = fmaf(xv, w3.z, acc[14]); acc[15] = fmaf(xv, w3.w, acc[15]);
    }

    if (hu0 < H_) {
        #pragma unroll
        for (int k = 0; k < 16; k++) {
            int h = hu0 + k;
            g_A[((b * H_) + h) * N_ + n] = acc[k] + b1[h];
        }
    } else {
        #pragma unroll
        for (int k = 0; k < 16; k++) {
            int h = hu0 + k - H_;
            g_Bv[((b * H_) + h) * N_ + n] = acc[k];
        }
    }
}

// ---------------------------------------------------------------------------
// Kernel 2: y[b,i,j] = (j>i) * ( b2 + P'_i + Q'_j + sum_h w'_h |A_ih + B_jh| )
// with w' = w/2, P' = sum w' A, Q' = sum w' B  (relu(u) = (u+|u|)/2).
// 32(i) x 64(j) tiles, 256 threads, 2i x 4j per thread, packed f32x2 over j.
// grid (8, 16, B). Tiles fully below the diagonal are zero-filled and exit.
// ---------------------------------------------------------------------------
__global__ void __launch_bounds__(256) pairwise_score(
        const float* __restrict__ W2,
        const float* __restrict__ b2,
        float* __restrict__ out) {
    const int Jt  = blockIdx.x;   // 0..7   (j tile of 64)
    const int It  = blockIdx.y;   // 0..15  (i tile of 32)
    const int b   = blockIdx.z;
    const int tid = threadIdx.x;
    float* outb = out + b * N_ * N_;

    if (It >= 2 * Jt + 2) {       // entirely below diagonal -> zeros
        const float4 z = make_float4(0.f, 0.f, 0.f, 0.f);
        #pragma unroll
        for (int r = 0; r < 2; r++) {
            int l  = tid + 256 * r;    // float4 index 0..511
            int ii = l >> 4;
            int j4 = l & 15;
            *(float4*)(outb + (It * 32 + ii) * N_ + Jt * 64 + j4 * 4) = z;
        }
        return;
    }

    __shared__ unsigned long long Adup[64 * 32];  // [hh][ii] = (a,a)
    __shared__ float Bsh[64 * 64];                // [hh][jj]
    __shared__ unsigned long long Wsh2[64];       // (w/2, w/2)
    __shared__ float Psh[32];
    __shared__ float Qsh[64];

    const int ti  = tid >> 4;     // 0..15
    const int tj  = tid & 15;     // 0..15
    const int il0 = ti * 2;
    const int jl0 = tj * 4;

    unsigned long long acc00 = 0ULL, acc01 = 0ULL, acc10 = 0ULL, acc11 = 0ULL;
    float P_loc = 0.f, Q_loc = 0.f;

    #pragma unroll
    for (int hb = 0; hb < 2; hb++) {
        __syncthreads();
        const float* Ag = g_A  + ((b * H_) + hb * 64) * N_ + It * 32;
        const float* Bg = g_Bv + ((b * H_) + hb * 64) * N_ + Jt * 64;

        // Stage A duplicated as (a,a) pairs: [64 hh][32 ii]
        #pragma unroll
        for (int r = 0; r < 8; r++) {
            int l  = tid + 256 * r;    // 0..2047
            int hh = l >> 5;
            int ii = l & 31;
            unsigned long long aa = (unsigned long long)__float_as_uint(Ag[hh * N_ + ii]);
            Adup[hh * 32 + ii] = aa | (aa << 32);
        }
        // Stage B: [64 hh][64 jj]
        #pragma unroll
        for (int r = 0; r < 4; r++) {
            int l  = tid + 256 * r;    // float4 index 0..1023
            int hh = l >> 4;
            int j4 = l & 15;
            *(float4*)(Bsh + hh * 64 + j4 * 4) = *(const float4*)(Bg + hh * N_ + j4 * 4);
        }
        // Stage halved, duplicated W2
        if (tid < 64) {
            float w = 0.5f * W2[hb * 64 + tid];
            unsigned long long ww = (unsigned long long)__float_as_uint(w);
            Wsh2[tid] = ww | (ww << 32);
        }
        __syncthreads();

        // Rank-1 linear part: P'_i, Q'_j partials (subset of threads, tiny loop)
        if (tid < 96) {
            const float* Wf = (const float*)Wsh2;  // w' at index 2*hh
            if (tid < 32) {
                const float* Af = (const float*)Adup;  // a at index (hh*32+i)*2
                #pragma unroll 8
                for (int hh = 0; hh < 64; hh++)
                    P_loc = fmaf(Wf[2 * hh], Af[(hh * 32 + tid) * 2], P_loc);
            } else {
                int j = tid - 32;
                #pragma unroll 8
                for (int hh = 0; hh < 64; hh++)
                    Q_loc = fmaf(Wf[2 * hh], Bsh[hh * 64 + j], Q_loc);
            }
        }

        // Main loop: 2 packed ADD2/AND64/FMA2 groups per (p, j-pair)
        const unsigned long long* Ap = Adup + il0;
        const float* Bp = Bsh + jl0;
        const unsigned long long* Wp = Wsh2;
        #pragma unroll 8
        for (int hh = 0; hh < 64; hh++) {
            unsigned long long w2 = Wp[hh];
            unsigned long long a0 = Ap[hh * 32];
            unsigned long long a1 = Ap[hh * 32 + 1];
            ulonglong2 bb = *(const ulonglong2*)(Bp + hh * 64);

            unsigned long long u;
            u = f32x2_add(a0, bb.x) & ABS2_MASK; acc00 = f32x2_fma(u, w2, acc00);
            u = f32x2_add(a0, bb.y) & ABS2_MASK; acc01 = f32x2_fma(u, w2, acc01);
            u = f32x2_add(a1, bb.x) & ABS2_MASK; acc10 = f32x2_fma(u, w2, acc10);
            u = f32x2_add(a1, bb.y) & ABS2_MASK; acc11 = f32x2_fma(u, w2, acc11);
        }
    }

    // Publish P/Q (fold b2 into P)
    if (tid < 32)       Psh[tid]      = P_loc + b2[0];
    else if (tid < 96)  Qsh[tid - 32] = Q_loc;
    __syncthreads();

    // Epilogue
    float af[2][4];
    af[0][0] = __uint_as_float((unsigned)(acc00));
    af[0][1] = __uint_as_float((unsigned)(acc00 >> 32));
    af[0][2] = __uint_as_float((unsigned)(acc01));
    af[0][3] = __uint_as_float((unsigned)(acc01 >> 32));
    af[1][0] = __uint_as_float((unsigned)(acc10));
    af[1][1] = __uint_as_float((unsigned)(acc10 >> 32));
    af[1][2] = __uint_as_float((unsigned)(acc11));
    af[1][3] = __uint_as_float((unsigned)(acc11 >> 32));

    const int i0 = It * 32 + il0;
    const int j0 = Jt * 64 + jl0;
    const bool full = (It <= 2 * Jt - 1);   // min j in tile > max i in tile

    float q0 = Qsh[jl0], q1 = Qsh[jl0 + 1], q2 = Qsh[jl0 + 2], q3 = Qsh[jl0 + 3];
    #pragma unroll
    for (int p = 0; p < 2; p++) {
        int i = i0 + p;
        float pb = Psh[il0 + p];
        float4 v;
        v.x = pb + q0 + af[p][0];
        v.y = pb + q1 + af[p][1];
        v.z = pb + q2 + af[p][2];
        v.w = pb + q3 + af[p][3];
        if (!full) {   // diagonal tile: strict upper-triangle mask
            if (!(j0 + 0 > i)) v.x = 0.f;
            if (!(j0 + 1 > i)) v.y = 0.f;
            if (!(j0 + 2 > i)) v.z = 0.f;
            if (!(j0 + 3 > i)) v.w = 0.f;
        }
        *(float4*)(outb + i * N_ + j0) = v;
    }
}

// ---------------------------------------------------------------------------
// Inputs: 0:x (B,C,N) f32, 1:W1 (2C,H) f32, 2:b1 (H) f32, 3:W2 (H,1) f32,
//         4:b2 (1) f32.  Output: (B,N,N) f32.
// ---------------------------------------------------------------------------
extern "C" void kernel_launch(void* const* d_in, const int* in_sizes, int n_in,
                              void* d_out, int out_size) {
    const float* x  = (const float*)d_in[0];
    const float* W1 = (const float*)d_in[1];
    const float* b1 = (const float*)d_in[2];
    const float* W2 = (const float*)d_in[3];
    const float* b2 = (const float*)d_in[4];
    float* out = (float*)d_out;

    dim3 g1(N_ / 256, (2 * H_) / 16, B_);   // (2, 16, 4)
    precompute_AB<<<g1, 256>>>(x, W1, b1);

    dim3 g2(N_ / 64, N_ / 32, B_);          // (8, 16, 4)
    pairwise_score<<<g2, 256>>>(W2, b2, out);
}